// round 1
// baseline (speedup 1.0000x reference)
#include <cuda_runtime.h>

#define BATCH 32
#define NTOK  1024
#define CH    512
#define DQKD  64

// Scratch (device globals — no runtime allocation allowed)
__device__ float g_q[BATCH * NTOK * DQKD];          // 8 MB
__device__ float g_k[BATCH * NTOK * DQKD];          // 8 MB
__device__ float g_v[(size_t)BATCH * NTOK * CH];    // 64 MB
__device__ float g_s[(size_t)BATCH * NTOK * NTOK];  // 128 MB (scores/probs)

// ---------------------------------------------------------------------------
// Kernel 1: QKV projection.  out[m, j] = x[m,:] @ Wcat[:, j] + bcat[j]
// M = 32768 tokens, 640 output cols = [q(64) | k(64) | v(512)]
// grid = (10 col-tiles of 64, 512 row-tiles of 64), 256 threads
// ---------------------------------------------------------------------------
__global__ void qkv_kernel(const float* __restrict__ x,
                           const float* __restrict__ wq, const float* __restrict__ bq,
                           const float* __restrict__ wk, const float* __restrict__ bk,
                           const float* __restrict__ wv, const float* __restrict__ bv)
{
    const int BK = 32;
    __shared__ float As[32][65];   // [k][m], padded
    __shared__ float Bs[32][64];   // [k][j]

    const int tid = threadIdx.x;
    const int tx = tid & 15, ty = tid >> 4;
    const int m0 = blockIdx.y * 64;

    const float* wptr; const float* bptr; float* outp;
    int ldw, ldo, jloc0;
    if (blockIdx.x == 0)      { wptr = wq; bptr = bq; outp = g_q; ldw = DQKD; ldo = DQKD; jloc0 = 0; }
    else if (blockIdx.x == 1) { wptr = wk; bptr = bk; outp = g_k; ldw = DQKD; ldo = DQKD; jloc0 = 0; }
    else                      { wptr = wv; bptr = bv; outp = g_v; ldw = CH;   ldo = CH;   jloc0 = (blockIdx.x - 2) * 64; }

    float acc[4][4] = {};
    for (int k0 = 0; k0 < CH; k0 += BK) {
        #pragma unroll
        for (int i = 0; i < 8; i++) {              // A tile 64x32 -> transposed
            int idx = tid + i * 256;
            int m = idx >> 5, k = idx & 31;
            As[k][m] = x[(size_t)(m0 + m) * CH + k0 + k];
        }
        #pragma unroll
        for (int i = 0; i < 8; i++) {              // B tile 32x64
            int idx = tid + i * 256;
            int k = idx >> 6, j = idx & 63;
            Bs[k][j] = wptr[(size_t)(k0 + k) * ldw + jloc0 + j];
        }
        __syncthreads();
        #pragma unroll
        for (int k = 0; k < BK; k++) {
            float a[4], b[4];
            #pragma unroll
            for (int i = 0; i < 4; i++) a[i] = As[k][ty * 4 + i];
            #pragma unroll
            for (int j = 0; j < 4; j++) b[j] = Bs[k][tx * 4 + j];
            #pragma unroll
            for (int i = 0; i < 4; i++)
                #pragma unroll
                for (int j = 0; j < 4; j++)
                    acc[i][j] += a[i] * b[j];
        }
        __syncthreads();
    }
    #pragma unroll
    for (int i = 0; i < 4; i++) {
        int m = m0 + ty * 4 + i;
        #pragma unroll
        for (int j = 0; j < 4; j++) {
            int jl = jloc0 + tx * 4 + j;
            outp[(size_t)m * ldo + jl] = acc[i][j] + bptr[jl];
        }
    }
}

// ---------------------------------------------------------------------------
// Kernel 2: scores.  S[b,i,j] = scale * q[b,i,:] . k[b,j,:]   (K = 64 fits)
// grid = (16 col-tiles, 16 row-tiles, 32 batches), 256 threads
// ---------------------------------------------------------------------------
__global__ void scores_kernel()
{
    __shared__ float Qs[64][65];   // [d][m]
    __shared__ float Ks[64][65];   // [d][j]

    const int b = blockIdx.z;
    const int i0 = blockIdx.y * 64, j0 = blockIdx.x * 64;
    const int tid = threadIdx.x;
    const int tx = tid & 15, ty = tid >> 4;

    const float* qb = g_q + (size_t)b * NTOK * DQKD;
    const float* kb = g_k + (size_t)b * NTOK * DQKD;

    #pragma unroll
    for (int i = 0; i < 16; i++) {
        int idx = tid + i * 256;   // 4096 elems
        int m = idx >> 6, d = idx & 63;
        Qs[d][m] = qb[(size_t)(i0 + m) * DQKD + d];
        Ks[d][m] = kb[(size_t)(j0 + m) * DQKD + d];
    }
    __syncthreads();

    float acc[4][4] = {};
    #pragma unroll 8
    for (int d = 0; d < 64; d++) {
        float a[4], c[4];
        #pragma unroll
        for (int i = 0; i < 4; i++) a[i] = Qs[d][ty * 4 + i];
        #pragma unroll
        for (int j = 0; j < 4; j++) c[j] = Ks[d][tx * 4 + j];
        #pragma unroll
        for (int i = 0; i < 4; i++)
            #pragma unroll
            for (int j = 0; j < 4; j++)
                acc[i][j] += a[i] * c[j];
    }

    const float scale = 0.125f;  // 1/sqrt(64)
    float* srow = g_s + (size_t)b * NTOK * NTOK;
    #pragma unroll
    for (int i = 0; i < 4; i++)
        #pragma unroll
        for (int j = 0; j < 4; j++)
            srow[(size_t)(i0 + ty * 4 + i) * NTOK + j0 + tx * 4 + j] = acc[i][j] * scale;
}

// ---------------------------------------------------------------------------
// Kernel 3: row softmax over g_s.  One block (256 thr) per row of 1024.
// ---------------------------------------------------------------------------
__global__ void softmax_kernel()
{
    float* p = g_s + (size_t)blockIdx.x * NTOK;
    const int tid = threadIdx.x;
    __shared__ float red[256];

    float v[4];
    float mx = -1e30f;
    #pragma unroll
    for (int i = 0; i < 4; i++) { v[i] = p[tid + i * 256]; mx = fmaxf(mx, v[i]); }

    red[tid] = mx; __syncthreads();
    for (int s = 128; s > 0; s >>= 1) {
        if (tid < s) red[tid] = fmaxf(red[tid], red[tid + s]);
        __syncthreads();
    }
    mx = red[0]; __syncthreads();

    float sum = 0.f;
    #pragma unroll
    for (int i = 0; i < 4; i++) { v[i] = __expf(v[i] - mx); sum += v[i]; }

    red[tid] = sum; __syncthreads();
    for (int s = 128; s > 0; s >>= 1) {
        if (tid < s) red[tid] += red[tid + s];
        __syncthreads();
    }
    float inv = 1.0f / red[0];
    #pragma unroll
    for (int i = 0; i < 4; i++) p[tid + i * 256] = v[i] * inv;
}

// ---------------------------------------------------------------------------
// Kernel 4: O = P @ V + x.  Per-batch GEMM M=1024, N=512, K=1024.
// grid = (8 col-tiles, 16 row-tiles, 32 batches), 256 threads
// ---------------------------------------------------------------------------
__global__ void av_kernel(const float* __restrict__ x, float* __restrict__ out)
{
    const int BK = 32;
    __shared__ float Ps[32][65];   // [k][m]
    __shared__ float Vs[32][64];   // [k][c]

    const int b = blockIdx.z;
    const int i0 = blockIdx.y * 64, c0 = blockIdx.x * 64;
    const int tid = threadIdx.x;
    const int tx = tid & 15, ty = tid >> 4;

    const float* pb = g_s + (size_t)b * NTOK * NTOK;
    const float* vb = g_v + (size_t)b * NTOK * CH;

    float acc[4][4] = {};
    for (int k0 = 0; k0 < NTOK; k0 += BK) {
        #pragma unroll
        for (int i = 0; i < 8; i++) {
            int idx = tid + i * 256;
            int m = idx >> 5, k = idx & 31;
            Ps[k][m] = pb[(size_t)(i0 + m) * NTOK + k0 + k];
        }
        #pragma unroll
        for (int i = 0; i < 8; i++) {
            int idx = tid + i * 256;
            int k = idx >> 6, j = idx & 63;
            Vs[k][j] = vb[(size_t)(k0 + k) * CH + c0 + j];
        }
        __syncthreads();
        #pragma unroll
        for (int k = 0; k < BK; k++) {
            float a[4], bb[4];
            #pragma unroll
            for (int i = 0; i < 4; i++) a[i] = Ps[k][ty * 4 + i];
            #pragma unroll
            for (int j = 0; j < 4; j++) bb[j] = Vs[k][tx * 4 + j];
            #pragma unroll
            for (int i = 0; i < 4; i++)
                #pragma unroll
                for (int j = 0; j < 4; j++)
                    acc[i][j] += a[i] * bb[j];
        }
        __syncthreads();
    }
    #pragma unroll
    for (int i = 0; i < 4; i++)
        #pragma unroll
        for (int j = 0; j < 4; j++) {
            size_t oi = ((size_t)b * NTOK + i0 + ty * 4 + i) * CH + c0 + tx * 4 + j;
            out[oi] = acc[i][j] + x[oi];
        }
}

// ---------------------------------------------------------------------------
extern "C" void kernel_launch(void* const* d_in, const int* in_sizes, int n_in,
                              void* d_out, int out_size)
{
    const float* x  = (const float*)d_in[0];
    const float* wq = (const float*)d_in[1];
    const float* bq = (const float*)d_in[2];
    const float* wk = (const float*)d_in[3];
    const float* bk = (const float*)d_in[4];
    const float* wv = (const float*)d_in[5];
    const float* bv = (const float*)d_in[6];
    float* out = (float*)d_out;

    qkv_kernel<<<dim3(10, 512), 256>>>(x, wq, bq, wk, bk, wv, bv);
    scores_kernel<<<dim3(16, 16, 32), 256>>>();
    softmax_kernel<<<BATCH * NTOK, 256>>>();
    av_kernel<<<dim3(8, 16, 32), 256>>>(x, out);
}

// round 3
// speedup vs baseline: 2.6592x; 2.6592x over previous
#include <cuda_runtime.h>
#include <cuda_bf16.h>
#include <cstdint>

#define BATCH 32
#define NTOK  1024
#define CH    512
#define DQKD  64

// ---------------------------------------------------------------------------
// Device-global scratch (no runtime allocation allowed)
// ---------------------------------------------------------------------------
__device__ __align__(128) __nv_bfloat16 g_xhi[(size_t)BATCH * NTOK * CH];    // 32 MB
__device__ __align__(128) __nv_bfloat16 g_xlo[(size_t)BATCH * NTOK * CH];    // 32 MB
__device__ __align__(128) __nv_bfloat16 g_wthi[640 * CH];                    // 640 KB  W^T [n][k]
__device__ __align__(128) __nv_bfloat16 g_wtlo[640 * CH];
__device__ __align__(128) __nv_bfloat16 g_qhi[(size_t)BATCH * NTOK * DQKD];  // 4 MB
__device__ __align__(128) __nv_bfloat16 g_qlo[(size_t)BATCH * NTOK * DQKD];
__device__ __align__(128) __nv_bfloat16 g_khi[(size_t)BATCH * NTOK * DQKD];
__device__ __align__(128) __nv_bfloat16 g_klo[(size_t)BATCH * NTOK * DQKD];
__device__ __align__(128) __nv_bfloat16 g_vthi[(size_t)BATCH * CH * NTOK];   // 32 MB  V^T [b][c][m]
__device__ __align__(128) __nv_bfloat16 g_vtlo[(size_t)BATCH * CH * NTOK];
__device__ __align__(128) float         g_s[(size_t)BATCH * NTOK * NTOK];    // 128 MB scores
__device__ __align__(128) __nv_bfloat16 g_phi[(size_t)BATCH * NTOK * NTOK];  // 64 MB  P hi
__device__ __align__(128) __nv_bfloat16 g_plo[(size_t)BATCH * NTOK * NTOK];  // 64 MB  P lo

// ---------------------------------------------------------------------------
// PTX helpers (baseline ISA only: works on compute_103 / sm_103)
// ---------------------------------------------------------------------------
__device__ __forceinline__ uint32_t smem_u32(const void* p) {
    uint32_t a;
    asm("{ .reg .u64 t; cvta.to.shared.u64 t, %1; cvt.u32.u64 %0, t; }" : "=r"(a) : "l"(p));
    return a;
}
__device__ __forceinline__ void cp16(uint32_t dst, const void* src) {
    asm volatile("cp.async.cg.shared.global [%0], [%1], 16;" :: "r"(dst), "l"(src));
}
#define CP_COMMIT() asm volatile("cp.async.commit_group;" ::: "memory")
#define CP_WAIT1()  asm volatile("cp.async.wait_group 1;" ::: "memory")

__device__ __forceinline__ void ldm_x4(uint32_t* r, uint32_t addr) {
    asm volatile("ldmatrix.sync.aligned.m8n8.x4.shared.b16 {%0,%1,%2,%3}, [%4];"
                 : "=r"(r[0]), "=r"(r[1]), "=r"(r[2]), "=r"(r[3]) : "r"(addr));
}
__device__ __forceinline__ void ldm_x2(uint32_t* r, uint32_t addr) {
    asm volatile("ldmatrix.sync.aligned.m8n8.x2.shared.b16 {%0,%1}, [%2];"
                 : "=r"(r[0]), "=r"(r[1]) : "r"(addr));
}
__device__ __forceinline__ void mma_bf16(float* c, const uint32_t* a, const uint32_t* b) {
    asm volatile(
        "mma.sync.aligned.m16n8k16.row.col.f32.bf16.bf16.f32 "
        "{%0,%1,%2,%3}, {%4,%5,%6,%7}, {%8,%9}, {%0,%1,%2,%3};"
        : "+f"(c[0]), "+f"(c[1]), "+f"(c[2]), "+f"(c[3])
        : "r"(a[0]), "r"(a[1]), "r"(a[2]), "r"(a[3]), "r"(b[0]), "r"(b[1]));
}

// ---------------------------------------------------------------------------
// Shared-memory tiling constants
//   CTA tile 128x128, BK=32, K-major, rows padded to 40 bf16 (80 B) so that
//   ldmatrix 8-row groups hit distinct banks (stride 80B -> banks {0,20,8,28,16,4,24,12}).
//   Two stages, 4 matrices (Ahi, Alo, Bhi, Blo) per stage.
// ---------------------------------------------------------------------------
#define ROW_B   80                   // bytes per padded smem row
#define TILE_B  (128 * ROW_B)        // 10240 B per matrix tile
#define OA_HI   0
#define OA_LO   (1 * TILE_B)
#define OB_HI   (2 * TILE_B)
#define OB_LO   (3 * TILE_B)
#define STAGE_B (4 * TILE_B)         // 40960 B
#define SMEM_B  (2 * STAGE_B)        // 81920 B dynamic smem

// ---------------------------------------------------------------------------
// Templated split-bf16 GEMM mainloop.
// C[128x128] (per CTA) = Ahi/lo[128xK] * (Bhi/lo[128xK])^T, 3 products.
// acc[mb][nb][ci], warp tile 64x32 (8 warps as 2x4).
// ---------------------------------------------------------------------------
template<int LDA, int LDB, int NCHUNK>
__device__ __forceinline__ void gemm_loop(
    float (&acc)[4][4][4], uint32_t sb,
    const __nv_bfloat16* __restrict__ gAhi, const __nv_bfloat16* __restrict__ gAlo,
    const __nv_bfloat16* __restrict__ gBhi, const __nv_bfloat16* __restrict__ gBlo)
{
    const int tid  = threadIdx.x;
    const int wid  = tid >> 5;
    const int lane = tid & 31;
    const int mw   = (wid >> 2) * 64;   // warp row offset in CTA tile
    const int nw   = (wid & 3) * 32;    // warp col offset

    const uint32_t a_l = (uint32_t)((lane & 15) * ROW_B + (lane >> 4) * 16);
    const uint32_t b_l = (uint32_t)((lane & 7) * ROW_B + ((lane >> 3) & 1) * 16);

    auto load_stage = [&](int chunk, int st) {
        const int k0 = chunk * 32;
        const uint32_t base = sb + (uint32_t)st * STAGE_B;
        #pragma unroll
        for (int t = 0; t < 2; t++) {
            int u = tid + t * 256;          // 0..511
            int row = u >> 2, seg = u & 3;
            uint32_t so = base + (uint32_t)(row * ROW_B + seg * 16);
            size_t ka = (size_t)row * LDA + k0 + seg * 8;
            size_t kb = (size_t)row * LDB + k0 + seg * 8;
            cp16(so + OA_HI, gAhi + ka);
            cp16(so + OA_LO, gAlo + ka);
            cp16(so + OB_HI, gBhi + kb);
            cp16(so + OB_LO, gBlo + kb);
        }
        CP_COMMIT();
    };

    load_stage(0, 0);

    for (int c = 0; c < NCHUNK; c++) {
        if (c + 1 < NCHUNK) load_stage(c + 1, (c + 1) & 1);
        else                CP_COMMIT();     // empty group keeps wait count uniform
        CP_WAIT1();
        __syncthreads();

        const uint32_t stb = sb + (uint32_t)(c & 1) * STAGE_B;
        #pragma unroll
        for (int kk = 0; kk < 32; kk += 16) {
            uint32_t bh[4][2], bl[4][2];
            #pragma unroll
            for (int nb = 0; nb < 4; nb++) {
                uint32_t ba = stb + (uint32_t)((nw + nb * 8) * ROW_B + kk * 2) + b_l;
                ldm_x2(bh[nb], ba + OB_HI);
                ldm_x2(bl[nb], ba + OB_LO);
            }
            #pragma unroll
            for (int mb = 0; mb < 4; mb++) {
                uint32_t ah[4], al[4];
                uint32_t aa = stb + (uint32_t)((mw + mb * 16) * ROW_B + kk * 2) + a_l;
                ldm_x4(ah, aa + OA_HI);
                ldm_x4(al, aa + OA_LO);
                #pragma unroll
                for (int nb = 0; nb < 4; nb++) {
                    mma_bf16(acc[mb][nb], ah, bh[nb]);
                    mma_bf16(acc[mb][nb], ah, bl[nb]);
                    mma_bf16(acc[mb][nb], al, bh[nb]);
                }
            }
        }
        __syncthreads();
    }
}

// ---------------------------------------------------------------------------
// Prep: split x into bf16 hi/lo
// ---------------------------------------------------------------------------
__global__ void convx_kernel(const float* __restrict__ x)
{
    size_t i = ((size_t)blockIdx.x * 256 + threadIdx.x) * 4;
    float4 v = *(const float4*)(x + i);
    __nv_bfloat16 h0 = __float2bfloat16(v.x), h1 = __float2bfloat16(v.y);
    __nv_bfloat16 h2 = __float2bfloat16(v.z), h3 = __float2bfloat16(v.w);
    __nv_bfloat162 hA; hA.x = h0; hA.y = h1;
    __nv_bfloat162 hB; hB.x = h2; hB.y = h3;
    *(__nv_bfloat162*)(g_xhi + i)     = hA;
    *(__nv_bfloat162*)(g_xhi + i + 2) = hB;
    __nv_bfloat162 lA, lB;
    lA.x = __float2bfloat16(v.x - __bfloat162float(h0));
    lA.y = __float2bfloat16(v.y - __bfloat162float(h1));
    lB.x = __float2bfloat16(v.z - __bfloat162float(h2));
    lB.y = __float2bfloat16(v.w - __bfloat162float(h3));
    *(__nv_bfloat162*)(g_xlo + i)     = lA;
    *(__nv_bfloat162*)(g_xlo + i + 2) = lB;
}

// ---------------------------------------------------------------------------
// Prep: W^T hi/lo.  n in [0,640): n<64 -> wq col, n<128 -> wk, else wv.
// ---------------------------------------------------------------------------
__global__ void convw_kernel(const float* __restrict__ wq,
                             const float* __restrict__ wk,
                             const float* __restrict__ wv)
{
    int idx = blockIdx.x * 256 + threadIdx.x;       // 640*512
    int n = idx >> 9, k = idx & 511;
    float v;
    if (n < 64)        v = wq[k * DQKD + n];
    else if (n < 128)  v = wk[k * DQKD + (n - 64)];
    else               v = wv[k * CH + (n - 128)];
    __nv_bfloat16 hi = __float2bfloat16(v);
    g_wthi[idx] = hi;
    g_wtlo[idx] = __float2bfloat16(v - __bfloat162float(hi));
}

// ---------------------------------------------------------------------------
// Kernel 1: QKV projection. C = x @ Wcat + b. M=32768, N=640, K=512.
// grid = (5 col-tiles, 256 row-tiles). Epilogue splits outputs into bf16 hi/lo
// and writes q, k (K-major) and V^T (c-major rows) directly.
// ---------------------------------------------------------------------------
__global__ void __launch_bounds__(256)
qkv_tc_kernel(const float* __restrict__ bq, const float* __restrict__ bk,
              const float* __restrict__ bv)
{
    extern __shared__ char dsmem[];
    const uint32_t sb = smem_u32(dsmem);
    const int m0 = blockIdx.y * 128;
    const int n0 = blockIdx.x * 128;

    float acc[4][4][4] = {};
    gemm_loop<CH, CH, 16>(acc, sb,
                          g_xhi + (size_t)m0 * CH, g_xlo + (size_t)m0 * CH,
                          g_wthi + (size_t)n0 * CH, g_wtlo + (size_t)n0 * CH);

    const int wid = threadIdx.x >> 5, lane = threadIdx.x & 31;
    const int mw = (wid >> 2) * 64, nw = (wid & 3) * 32;
    const int gid = lane >> 2, tig = lane & 3;

    #pragma unroll
    for (int mb = 0; mb < 4; mb++)
        #pragma unroll
        for (int nb = 0; nb < 4; nb++)
            #pragma unroll
            for (int ci = 0; ci < 4; ci++) {
                int row = m0 + mw + mb * 16 + gid + ((ci >> 1) << 3);
                int col = n0 + nw + nb * 8 + tig * 2 + (ci & 1);
                float bias = (col < 64) ? bq[col] : (col < 128) ? bk[col - 64] : bv[col - 128];
                float v = acc[mb][nb][ci] + bias;
                __nv_bfloat16 hi = __float2bfloat16(v);
                __nv_bfloat16 lo = __float2bfloat16(v - __bfloat162float(hi));
                if (col < 64) {
                    size_t o = (size_t)row * DQKD + col;
                    g_qhi[o] = hi; g_qlo[o] = lo;
                } else if (col < 128) {
                    size_t o = (size_t)row * DQKD + (col - 64);
                    g_khi[o] = hi; g_klo[o] = lo;
                } else {
                    int b = row >> 10, t = row & 1023, cc = col - 128;
                    size_t o = ((size_t)b * CH + cc) * NTOK + t;
                    g_vthi[o] = hi; g_vtlo[o] = lo;
                }
            }
}

// ---------------------------------------------------------------------------
// Kernel 2: scores. S[b] = 0.125 * q[b] @ k[b]^T.  M=N=1024, K=64.
// grid = (8, 8, 32)
// ---------------------------------------------------------------------------
__global__ void __launch_bounds__(256)
scores_tc_kernel()
{
    extern __shared__ char dsmem[];
    const uint32_t sb = smem_u32(dsmem);
    const int b = blockIdx.z;
    const int i0 = blockIdx.y * 128, j0 = blockIdx.x * 128;

    const size_t qoff = ((size_t)b * NTOK + i0) * DQKD;
    const size_t koff = ((size_t)b * NTOK + j0) * DQKD;

    float acc[4][4][4] = {};
    gemm_loop<DQKD, DQKD, 2>(acc, sb, g_qhi + qoff, g_qlo + qoff,
                             g_khi + koff, g_klo + koff);

    const int wid = threadIdx.x >> 5, lane = threadIdx.x & 31;
    const int mw = (wid >> 2) * 64, nw = (wid & 3) * 32;
    const int gid = lane >> 2, tig = lane & 3;

    float* srow = g_s + (size_t)b * NTOK * NTOK;
    #pragma unroll
    for (int mb = 0; mb < 4; mb++)
        #pragma unroll
        for (int nb = 0; nb < 4; nb++)
            #pragma unroll
            for (int h = 0; h < 2; h++) {
                int row = i0 + mw + mb * 16 + gid + h * 8;
                int col = j0 + nw + nb * 8 + tig * 2;
                float2 o;
                o.x = acc[mb][nb][h * 2 + 0] * 0.125f;
                o.y = acc[mb][nb][h * 2 + 1] * 0.125f;
                *(float2*)(srow + (size_t)row * NTOK + col) = o;
            }
}

// ---------------------------------------------------------------------------
// Kernel 3: row softmax, writes P split into bf16 hi/lo
// ---------------------------------------------------------------------------
__global__ void softmax_kernel()
{
    const size_t rb = (size_t)blockIdx.x * NTOK;
    const float* p = g_s + rb;
    const int tid = threadIdx.x;
    __shared__ float red[256];

    float v[4];
    float mx = -1e30f;
    #pragma unroll
    for (int i = 0; i < 4; i++) { v[i] = p[tid + i * 256]; mx = fmaxf(mx, v[i]); }

    red[tid] = mx; __syncthreads();
    for (int s = 128; s > 0; s >>= 1) {
        if (tid < s) red[tid] = fmaxf(red[tid], red[tid + s]);
        __syncthreads();
    }
    mx = red[0]; __syncthreads();

    float sum = 0.f;
    #pragma unroll
    for (int i = 0; i < 4; i++) { v[i] = __expf(v[i] - mx); sum += v[i]; }

    red[tid] = sum; __syncthreads();
    for (int s = 128; s > 0; s >>= 1) {
        if (tid < s) red[tid] += red[tid + s];
        __syncthreads();
    }
    float inv = 1.0f / red[0];
    #pragma unroll
    for (int i = 0; i < 4; i++) {
        float pv = v[i] * inv;
        __nv_bfloat16 hi = __float2bfloat16(pv);
        g_phi[rb + tid + i * 256] = hi;
        g_plo[rb + tid + i * 256] = __float2bfloat16(pv - __bfloat162float(hi));
    }
}

// ---------------------------------------------------------------------------
// Kernel 4: O = P @ V + x.  M=1024 (per batch), N=512, K=1024.
// grid = (4, 8, 32)
// ---------------------------------------------------------------------------
__global__ void __launch_bounds__(256)
av_tc_kernel(const float* __restrict__ x, float* __restrict__ out)
{
    extern __shared__ char dsmem[];
    const uint32_t sb = smem_u32(dsmem);
    const int b = blockIdx.z;
    const int i0 = blockIdx.y * 128, c0 = blockIdx.x * 128;

    const size_t poff = ((size_t)b * NTOK + i0) * NTOK;
    const size_t voff = ((size_t)b * CH + c0) * NTOK;

    float acc[4][4][4] = {};
    gemm_loop<NTOK, NTOK, 32>(acc, sb, g_phi + poff, g_plo + poff,
                              g_vthi + voff, g_vtlo + voff);

    const int wid = threadIdx.x >> 5, lane = threadIdx.x & 31;
    const int mw = (wid >> 2) * 64, nw = (wid & 3) * 32;
    const int gid = lane >> 2, tig = lane & 3;

    #pragma unroll
    for (int mb = 0; mb < 4; mb++)
        #pragma unroll
        for (int nb = 0; nb < 4; nb++)
            #pragma unroll
            for (int h = 0; h < 2; h++) {
                int row = i0 + mw + mb * 16 + gid + h * 8;
                int col = c0 + nw + nb * 8 + tig * 2;
                size_t o = ((size_t)b * NTOK + row) * CH + col;
                float2 xv = *(const float2*)(x + o);
                float2 ov;
                ov.x = acc[mb][nb][h * 2 + 0] + xv.x;
                ov.y = acc[mb][nb][h * 2 + 1] + xv.y;
                *(float2*)(out + o) = ov;
            }
}

// ---------------------------------------------------------------------------
extern "C" void kernel_launch(void* const* d_in, const int* in_sizes, int n_in,
                              void* d_out, int out_size)
{
    const float* x  = (const float*)d_in[0];
    const float* wq = (const float*)d_in[1];
    const float* bq = (const float*)d_in[2];
    const float* wk = (const float*)d_in[3];
    const float* bk = (const float*)d_in[4];
    const float* wv = (const float*)d_in[5];
    const float* bv = (const float*)d_in[6];
    float* out = (float*)d_out;

    cudaFuncSetAttribute(qkv_tc_kernel,    cudaFuncAttributeMaxDynamicSharedMemorySize, SMEM_B);
    cudaFuncSetAttribute(scores_tc_kernel, cudaFuncAttributeMaxDynamicSharedMemorySize, SMEM_B);
    cudaFuncSetAttribute(av_tc_kernel,     cudaFuncAttributeMaxDynamicSharedMemorySize, SMEM_B);

    convx_kernel<<<16384, 256>>>(x);
    convw_kernel<<<1280, 256>>>(wq, wk, wv);
    qkv_tc_kernel<<<dim3(5, 256), 256, SMEM_B>>>(bq, bk, bv);
    scores_tc_kernel<<<dim3(8, 8, 32), 256, SMEM_B>>>();
    softmax_kernel<<<BATCH * NTOK, 256>>>();
    av_tc_kernel<<<dim3(4, 8, 32), 256, SMEM_B>>>(x, out);
}

// round 4
// speedup vs baseline: 2.8195x; 1.0603x over previous
#include <cuda_runtime.h>
#include <cuda_bf16.h>
#include <cstdint>

#define BATCH 32
#define NTOK  1024
#define CH    512
#define DQKD  64

// ---------------------------------------------------------------------------
// Device-global scratch (no runtime allocation allowed)
// ---------------------------------------------------------------------------
__device__ __align__(128) __nv_bfloat16 g_xhi[(size_t)BATCH * NTOK * CH];    // 32 MB
__device__ __align__(128) __nv_bfloat16 g_xlo[(size_t)BATCH * NTOK * CH];    // 32 MB
__device__ __align__(128) __nv_bfloat16 g_wthi[640 * CH];                    // W^T [n][k]
__device__ __align__(128) __nv_bfloat16 g_wtlo[640 * CH];
__device__ __align__(128) __nv_bfloat16 g_qhi[(size_t)BATCH * NTOK * DQKD];
__device__ __align__(128) __nv_bfloat16 g_qlo[(size_t)BATCH * NTOK * DQKD];
__device__ __align__(128) __nv_bfloat16 g_khi[(size_t)BATCH * NTOK * DQKD];
__device__ __align__(128) __nv_bfloat16 g_klo[(size_t)BATCH * NTOK * DQKD];
__device__ __align__(128) __nv_bfloat16 g_vhi[(size_t)BATCH * NTOK * CH];    // V [b][m][c]
__device__ __align__(128) __nv_bfloat16 g_vlo[(size_t)BATCH * NTOK * CH];
__device__ __align__(128) float         g_s[(size_t)BATCH * NTOK * NTOK];    // 128 MB scores
__device__ __align__(128) __nv_bfloat16 g_phi[(size_t)BATCH * NTOK * NTOK];  // P hi
__device__ __align__(128) __nv_bfloat16 g_plo[(size_t)BATCH * NTOK * NTOK];  // P lo

// ---------------------------------------------------------------------------
// PTX helpers (baseline ISA: compiles for compute_103)
// ---------------------------------------------------------------------------
__device__ __forceinline__ uint32_t smem_u32(const void* p) {
    uint32_t a;
    asm("{ .reg .u64 t; cvta.to.shared.u64 t, %1; cvt.u32.u64 %0, t; }" : "=r"(a) : "l"(p));
    return a;
}
__device__ __forceinline__ void cp16(uint32_t dst, const void* src) {
    asm volatile("cp.async.cg.shared.global [%0], [%1], 16;" :: "r"(dst), "l"(src));
}
#define CP_COMMIT() asm volatile("cp.async.commit_group;" ::: "memory")
#define CP_WAIT1()  asm volatile("cp.async.wait_group 1;" ::: "memory")

__device__ __forceinline__ void ldm_x4(uint32_t* r, uint32_t addr) {
    asm volatile("ldmatrix.sync.aligned.m8n8.x4.shared.b16 {%0,%1,%2,%3}, [%4];"
                 : "=r"(r[0]), "=r"(r[1]), "=r"(r[2]), "=r"(r[3]) : "r"(addr));
}
__device__ __forceinline__ void ldm_x2(uint32_t* r, uint32_t addr) {
    asm volatile("ldmatrix.sync.aligned.m8n8.x2.shared.b16 {%0,%1}, [%2];"
                 : "=r"(r[0]), "=r"(r[1]) : "r"(addr));
}
__device__ __forceinline__ void ldm_x2_trans(uint32_t* r, uint32_t addr) {
    asm volatile("ldmatrix.sync.aligned.m8n8.x2.trans.shared.b16 {%0,%1}, [%2];"
                 : "=r"(r[0]), "=r"(r[1]) : "r"(addr));
}
__device__ __forceinline__ void mma_bf16(float* c, const uint32_t* a, const uint32_t* b) {
    asm volatile(
        "mma.sync.aligned.m16n8k16.row.col.f32.bf16.bf16.f32 "
        "{%0,%1,%2,%3}, {%4,%5,%6,%7}, {%8,%9}, {%0,%1,%2,%3};"
        : "+f"(c[0]), "+f"(c[1]), "+f"(c[2]), "+f"(c[3])
        : "r"(a[0]), "r"(a[1]), "r"(a[2]), "r"(a[3]), "r"(b[0]), "r"(b[1]));
}

// ---------------------------------------------------------------------------
// Shared tiling for qkv/scores (A and B both [rows][k], K-major, BK=32)
// ---------------------------------------------------------------------------
#define ROW_B   80                   // 32 bf16 = 64 B + 16 B pad
#define TILE_B  (128 * ROW_B)        // 10240
#define OA_HI   0
#define OA_LO   (1 * TILE_B)
#define OB_HI   (2 * TILE_B)
#define OB_LO   (3 * TILE_B)
#define STAGE_B (4 * TILE_B)         // 40960
#define SMEM_B  (2 * STAGE_B)        // 81920

// av tiling: A = P [128 tok][32 k] rows 80 B; B = V [32 k][128 c] rows 272 B
#define AV_BROW   272
#define AV_BTILE  (32 * AV_BROW)     // 8704
#define AV_OA_HI  0
#define AV_OA_LO  TILE_B
#define AV_OB_HI  (2 * TILE_B)
#define AV_OB_LO  (2 * TILE_B + AV_BTILE)
#define AV_STAGE  (2 * TILE_B + 2 * AV_BTILE)   // 37888
#define AV_SMEM   (2 * AV_STAGE)                // 75776

// ---------------------------------------------------------------------------
// Templated split-bf16 GEMM mainloop (A,B both [n/m][k] K-major).
// ---------------------------------------------------------------------------
template<int LDA, int LDB, int NCHUNK>
__device__ __forceinline__ void gemm_loop(
    float (&acc)[4][4][4], uint32_t sb,
    const __nv_bfloat16* __restrict__ gAhi, const __nv_bfloat16* __restrict__ gAlo,
    const __nv_bfloat16* __restrict__ gBhi, const __nv_bfloat16* __restrict__ gBlo)
{
    const int tid  = threadIdx.x;
    const int wid  = tid >> 5;
    const int lane = tid & 31;
    const int mw   = (wid >> 2) * 64;
    const int nw   = (wid & 3) * 32;

    const uint32_t a_l = (uint32_t)((lane & 15) * ROW_B + (lane >> 4) * 16);
    const uint32_t b_l = (uint32_t)((lane & 7) * ROW_B + ((lane >> 3) & 1) * 16);

    auto load_stage = [&](int chunk, int st) {
        const int k0 = chunk * 32;
        const uint32_t base = sb + (uint32_t)st * STAGE_B;
        #pragma unroll
        for (int t = 0; t < 2; t++) {
            int u = tid + t * 256;
            int row = u >> 2, seg = u & 3;
            uint32_t so = base + (uint32_t)(row * ROW_B + seg * 16);
            size_t ka = (size_t)row * LDA + k0 + seg * 8;
            size_t kb = (size_t)row * LDB + k0 + seg * 8;
            cp16(so + OA_HI, gAhi + ka);
            cp16(so + OA_LO, gAlo + ka);
            cp16(so + OB_HI, gBhi + kb);
            cp16(so + OB_LO, gBlo + kb);
        }
        CP_COMMIT();
    };

    load_stage(0, 0);

    for (int c = 0; c < NCHUNK; c++) {
        if (c + 1 < NCHUNK) load_stage(c + 1, (c + 1) & 1);
        else                CP_COMMIT();
        CP_WAIT1();
        __syncthreads();

        const uint32_t stb = sb + (uint32_t)(c & 1) * STAGE_B;
        #pragma unroll
        for (int kk = 0; kk < 32; kk += 16) {
            uint32_t bh[4][2], bl[4][2];
            #pragma unroll
            for (int nb = 0; nb < 4; nb++) {
                uint32_t ba = stb + (uint32_t)((nw + nb * 8) * ROW_B + kk * 2) + b_l;
                ldm_x2(bh[nb], ba + OB_HI);
                ldm_x2(bl[nb], ba + OB_LO);
            }
            #pragma unroll
            for (int mb = 0; mb < 4; mb++) {
                uint32_t ah[4], al[4];
                uint32_t aa = stb + (uint32_t)((mw + mb * 16) * ROW_B + kk * 2) + a_l;
                ldm_x4(ah, aa + OA_HI);
                ldm_x4(al, aa + OA_LO);
                #pragma unroll
                for (int nb = 0; nb < 4; nb++) {
                    mma_bf16(acc[mb][nb], ah, bh[nb]);
                    mma_bf16(acc[mb][nb], ah, bl[nb]);
                    mma_bf16(acc[mb][nb], al, bh[nb]);
                }
            }
        }
        __syncthreads();
    }
}

// ---------------------------------------------------------------------------
// Prep kernels
// ---------------------------------------------------------------------------
__global__ void convx_kernel(const float* __restrict__ x)
{
    size_t i = ((size_t)blockIdx.x * 256 + threadIdx.x) * 4;
    float4 v = *(const float4*)(x + i);
    __nv_bfloat16 h0 = __float2bfloat16(v.x), h1 = __float2bfloat16(v.y);
    __nv_bfloat16 h2 = __float2bfloat16(v.z), h3 = __float2bfloat16(v.w);
    __nv_bfloat162 hA; hA.x = h0; hA.y = h1;
    __nv_bfloat162 hB; hB.x = h2; hB.y = h3;
    *(__nv_bfloat162*)(g_xhi + i)     = hA;
    *(__nv_bfloat162*)(g_xhi + i + 2) = hB;
    __nv_bfloat162 lA, lB;
    lA.x = __float2bfloat16(v.x - __bfloat162float(h0));
    lA.y = __float2bfloat16(v.y - __bfloat162float(h1));
    lB.x = __float2bfloat16(v.z - __bfloat162float(h2));
    lB.y = __float2bfloat16(v.w - __bfloat162float(h3));
    *(__nv_bfloat162*)(g_xlo + i)     = lA;
    *(__nv_bfloat162*)(g_xlo + i + 2) = lB;
}

__global__ void convw_kernel(const float* __restrict__ wq,
                             const float* __restrict__ wk,
                             const float* __restrict__ wv)
{
    int idx = blockIdx.x * 256 + threadIdx.x;
    int n = idx >> 9, k = idx & 511;
    float v;
    if (n < 64)        v = wq[k * DQKD + n];
    else if (n < 128)  v = wk[k * DQKD + (n - 64)];
    else               v = wv[k * CH + (n - 128)];
    __nv_bfloat16 hi = __float2bfloat16(v);
    g_wthi[idx] = hi;
    g_wtlo[idx] = __float2bfloat16(v - __bfloat162float(hi));
}

// ---------------------------------------------------------------------------
// Kernel 1: QKV projection.  M=32768, N=640, K=512. grid (5, 256).
// Epilogue: q,k K-major hi/lo;  V natural [token][c] hi/lo (coalesced).
// ---------------------------------------------------------------------------
__global__ void __launch_bounds__(256, 2)
qkv_tc_kernel(const float* __restrict__ bq, const float* __restrict__ bk,
              const float* __restrict__ bv)
{
    extern __shared__ char dsmem[];
    const uint32_t sb = smem_u32(dsmem);
    const int m0 = blockIdx.y * 128;
    const int n0 = blockIdx.x * 128;

    float acc[4][4][4] = {};
    gemm_loop<CH, CH, 16>(acc, sb,
                          g_xhi + (size_t)m0 * CH, g_xlo + (size_t)m0 * CH,
                          g_wthi + (size_t)n0 * CH, g_wtlo + (size_t)n0 * CH);

    const int wid = threadIdx.x >> 5, lane = threadIdx.x & 31;
    const int mw = (wid >> 2) * 64, nw = (wid & 3) * 32;
    const int gid = lane >> 2, tig = lane & 3;

    #pragma unroll
    for (int mb = 0; mb < 4; mb++)
        #pragma unroll
        for (int nb = 0; nb < 4; nb++)
            #pragma unroll
            for (int ci = 0; ci < 4; ci++) {
                int row = m0 + mw + mb * 16 + gid + ((ci >> 1) << 3);
                int col = n0 + nw + nb * 8 + tig * 2 + (ci & 1);
                float bias = (col < 64) ? bq[col] : (col < 128) ? bk[col - 64] : bv[col - 128];
                float v = acc[mb][nb][ci] + bias;
                __nv_bfloat16 hi = __float2bfloat16(v);
                __nv_bfloat16 lo = __float2bfloat16(v - __bfloat162float(hi));
                if (col < 64) {
                    size_t o = (size_t)row * DQKD + col;
                    g_qhi[o] = hi; g_qlo[o] = lo;
                } else if (col < 128) {
                    size_t o = (size_t)row * DQKD + (col - 64);
                    g_khi[o] = hi; g_klo[o] = lo;
                } else {
                    size_t o = (size_t)row * CH + (col - 128);
                    g_vhi[o] = hi; g_vlo[o] = lo;
                }
            }
}

// ---------------------------------------------------------------------------
// Kernel 2: scores.  S[b] = 0.125 * q @ k^T.  grid (8, 8, 32).
// ---------------------------------------------------------------------------
__global__ void __launch_bounds__(256, 2)
scores_tc_kernel()
{
    extern __shared__ char dsmem[];
    const uint32_t sb = smem_u32(dsmem);
    const int b = blockIdx.z;
    const int i0 = blockIdx.y * 128, j0 = blockIdx.x * 128;

    const size_t qoff = ((size_t)b * NTOK + i0) * DQKD;
    const size_t koff = ((size_t)b * NTOK + j0) * DQKD;

    float acc[4][4][4] = {};
    gemm_loop<DQKD, DQKD, 2>(acc, sb, g_qhi + qoff, g_qlo + qoff,
                             g_khi + koff, g_klo + koff);

    const int wid = threadIdx.x >> 5, lane = threadIdx.x & 31;
    const int mw = (wid >> 2) * 64, nw = (wid & 3) * 32;
    const int gid = lane >> 2, tig = lane & 3;

    float* srow = g_s + (size_t)b * NTOK * NTOK;
    #pragma unroll
    for (int mb = 0; mb < 4; mb++)
        #pragma unroll
        for (int nb = 0; nb < 4; nb++)
            #pragma unroll
            for (int h = 0; h < 2; h++) {
                int row = i0 + mw + mb * 16 + gid + h * 8;
                int col = j0 + nw + nb * 8 + tig * 2;
                float2 o;
                o.x = acc[mb][nb][h * 2 + 0] * 0.125f;
                o.y = acc[mb][nb][h * 2 + 1] * 0.125f;
                *(float2*)(srow + (size_t)row * NTOK + col) = o;
            }
}

// ---------------------------------------------------------------------------
// Kernel 3: row softmax (vectorized), writes P as bf16 hi/lo
// ---------------------------------------------------------------------------
__global__ void __launch_bounds__(256)
softmax_kernel()
{
    const size_t rb = (size_t)blockIdx.x * NTOK;
    const int tid = threadIdx.x;
    __shared__ float redm[8];
    __shared__ float reds[8];

    float4 v = *(const float4*)(g_s + rb + tid * 4);
    float mx = fmaxf(fmaxf(v.x, v.y), fmaxf(v.z, v.w));
    #pragma unroll
    for (int o = 16; o > 0; o >>= 1) mx = fmaxf(mx, __shfl_xor_sync(~0u, mx, o));
    if ((tid & 31) == 0) redm[tid >> 5] = mx;
    __syncthreads();
    mx = redm[0];
    #pragma unroll
    for (int i = 1; i < 8; i++) mx = fmaxf(mx, redm[i]);

    v.x = __expf(v.x - mx); v.y = __expf(v.y - mx);
    v.z = __expf(v.z - mx); v.w = __expf(v.w - mx);
    float sum = (v.x + v.y) + (v.z + v.w);
    #pragma unroll
    for (int o = 16; o > 0; o >>= 1) sum += __shfl_xor_sync(~0u, sum, o);
    if ((tid & 31) == 0) reds[tid >> 5] = sum;
    __syncthreads();
    sum = reds[0];
    #pragma unroll
    for (int i = 1; i < 8; i++) sum += reds[i];
    float inv = 1.0f / sum;

    float p0 = v.x * inv, p1 = v.y * inv, p2 = v.z * inv, p3 = v.w * inv;
    __nv_bfloat162 h01, h23, l01, l23;
    h01.x = __float2bfloat16(p0); h01.y = __float2bfloat16(p1);
    h23.x = __float2bfloat16(p2); h23.y = __float2bfloat16(p3);
    l01.x = __float2bfloat16(p0 - __bfloat162float(h01.x));
    l01.y = __float2bfloat16(p1 - __bfloat162float(h01.y));
    l23.x = __float2bfloat16(p2 - __bfloat162float(h23.x));
    l23.y = __float2bfloat16(p3 - __bfloat162float(h23.y));
    *(__nv_bfloat162*)(g_phi + rb + tid * 4)     = h01;
    *(__nv_bfloat162*)(g_phi + rb + tid * 4 + 2) = h23;
    *(__nv_bfloat162*)(g_plo + rb + tid * 4)     = l01;
    *(__nv_bfloat162*)(g_plo + rb + tid * 4 + 2) = l23;
}

// ---------------------------------------------------------------------------
// Kernel 4: O = P @ V + x.  A = P [tok][k] K-major; B = V [k][c] row-major
// loaded with ldmatrix.trans.  grid (4, 8, 32).
// ---------------------------------------------------------------------------
__global__ void __launch_bounds__(256, 2)
av_tc_kernel(const float* __restrict__ x, float* __restrict__ out)
{
    extern __shared__ char dsmem[];
    const uint32_t sb = smem_u32(dsmem);
    const int b = blockIdx.z;
    const int i0 = blockIdx.y * 128, c0 = blockIdx.x * 128;
    const int tid = threadIdx.x;
    const int wid = tid >> 5, lane = tid & 31;
    const int mw = (wid >> 2) * 64, nw = (wid & 3) * 32;

    const __nv_bfloat16* pAhi = g_phi + ((size_t)b * NTOK + i0) * NTOK;
    const __nv_bfloat16* pAlo = g_plo + ((size_t)b * NTOK + i0) * NTOK;
    const __nv_bfloat16* pBhi = g_vhi + (size_t)b * NTOK * CH + c0;
    const __nv_bfloat16* pBlo = g_vlo + (size_t)b * NTOK * CH + c0;

    const uint32_t a_l = (uint32_t)((lane & 15) * ROW_B + (lane >> 4) * 16);
    const uint32_t b_l = (uint32_t)((lane & 15) * AV_BROW);

    auto load_stage = [&](int chunk, int st) {
        const int k0 = chunk * 32;
        const uint32_t base = sb + (uint32_t)st * AV_STAGE;
        // A: 128 rows x 64 B (hi & lo)
        #pragma unroll
        for (int t = 0; t < 2; t++) {
            int u = tid + t * 256;
            int row = u >> 2, seg = u & 3;
            uint32_t so = base + (uint32_t)(row * ROW_B + seg * 16);
            size_t ka = (size_t)row * NTOK + k0 + seg * 8;
            cp16(so + AV_OA_HI, pAhi + ka);
            cp16(so + AV_OA_LO, pAlo + ka);
        }
        // B: 32 rows (k) x 256 B (128 channels) (hi & lo)
        #pragma unroll
        for (int t = 0; t < 2; t++) {
            int u = tid + t * 256;
            int row = u >> 4, seg = u & 15;
            uint32_t so = base + (uint32_t)(row * AV_BROW + seg * 16);
            size_t kb = (size_t)(k0 + row) * CH + seg * 8;
            cp16(so + AV_OB_HI, pBhi + kb);
            cp16(so + AV_OB_LO, pBlo + kb);
        }
        CP_COMMIT();
    };

    float acc[4][4][4] = {};
    load_stage(0, 0);

    for (int c = 0; c < 32; c++) {
        if (c + 1 < 32) load_stage(c + 1, (c + 1) & 1);
        else            CP_COMMIT();
        CP_WAIT1();
        __syncthreads();

        const uint32_t stb = sb + (uint32_t)(c & 1) * AV_STAGE;
        #pragma unroll
        for (int kk = 0; kk < 32; kk += 16) {
            uint32_t bh[4][2], bl[4][2];
            #pragma unroll
            for (int nb = 0; nb < 4; nb++) {
                uint32_t ba = stb + (uint32_t)(kk * AV_BROW + (nw + nb * 8) * 2) + b_l;
                ldm_x2_trans(bh[nb], ba + AV_OB_HI);
                ldm_x2_trans(bl[nb], ba + AV_OB_LO);
            }
            #pragma unroll
            for (int mb = 0; mb < 4; mb++) {
                uint32_t ah[4], al[4];
                uint32_t aa = stb + (uint32_t)((mw + mb * 16) * ROW_B + kk * 2) + a_l;
                ldm_x4(ah, aa + AV_OA_HI);
                ldm_x4(al, aa + AV_OA_LO);
                #pragma unroll
                for (int nb = 0; nb < 4; nb++) {
                    mma_bf16(acc[mb][nb], ah, bh[nb]);
                    mma_bf16(acc[mb][nb], ah, bl[nb]);
                    mma_bf16(acc[mb][nb], al, bh[nb]);
                }
            }
        }
        __syncthreads();
    }

    const int gid = lane >> 2, tig = lane & 3;
    #pragma unroll
    for (int mb = 0; mb < 4; mb++)
        #pragma unroll
        for (int nb = 0; nb < 4; nb++)
            #pragma unroll
            for (int h = 0; h < 2; h++) {
                int row = i0 + mw + mb * 16 + gid + h * 8;
                int col = c0 + nw + nb * 8 + tig * 2;
                size_t o = ((size_t)b * NTOK + row) * CH + col;
                float2 xv = *(const float2*)(x + o);
                float2 ov;
                ov.x = acc[mb][nb][h * 2 + 0] + xv.x;
                ov.y = acc[mb][nb][h * 2 + 1] + xv.y;
                *(float2*)(out + o) = ov;
            }
}

// ---------------------------------------------------------------------------
extern "C" void kernel_launch(void* const* d_in, const int* in_sizes, int n_in,
                              void* d_out, int out_size)
{
    const float* x  = (const float*)d_in[0];
    const float* wq = (const float*)d_in[1];
    const float* bq = (const float*)d_in[2];
    const float* wk = (const float*)d_in[3];
    const float* bk = (const float*)d_in[4];
    const float* wv = (const float*)d_in[5];
    const float* bv = (const float*)d_in[6];
    float* out = (float*)d_out;

    cudaFuncSetAttribute(qkv_tc_kernel,    cudaFuncAttributeMaxDynamicSharedMemorySize, SMEM_B);
    cudaFuncSetAttribute(scores_tc_kernel, cudaFuncAttributeMaxDynamicSharedMemorySize, SMEM_B);
    cudaFuncSetAttribute(av_tc_kernel,     cudaFuncAttributeMaxDynamicSharedMemorySize, AV_SMEM);

    convx_kernel<<<16384, 256>>>(x);
    convw_kernel<<<1280, 256>>>(wq, wk, wv);
    qkv_tc_kernel<<<dim3(5, 256), 256, SMEM_B>>>(bq, bk, bv);
    scores_tc_kernel<<<dim3(8, 8, 32), 256, SMEM_B>>>();
    softmax_kernel<<<BATCH * NTOK, 256>>>();
    av_tc_kernel<<<dim3(4, 8, 32), 256, AV_SMEM>>>(x, out);
}

// round 7
// speedup vs baseline: 5.7584x; 2.0424x over previous
#include <cuda_runtime.h>
#include <cuda_fp16.h>
#include <cstdint>

#define BATCH 32
#define NTOK  1024
#define CH    512
#define DQKD  64

// ---------------------------------------------------------------------------
// Device-global scratch (fp16 single precision operands)
// ---------------------------------------------------------------------------
__device__ __align__(128) __half g_xh[(size_t)BATCH * NTOK * CH];     // 32 MB
__device__ __align__(128) __half g_wt[640 * CH];                      // W^T [n][k]
__device__ __align__(128) __half g_qh[(size_t)BATCH * NTOK * DQKD];
__device__ __align__(128) __half g_kh[(size_t)BATCH * NTOK * DQKD];
__device__ __align__(128) __half g_vh[(size_t)BATCH * NTOK * CH];     // V [b][m][c]
__device__ __align__(128) float  g_s[(size_t)BATCH * NTOK * NTOK];    // 128 MB scores
__device__ __align__(128) __half g_p[(size_t)BATCH * NTOK * NTOK];    // 64 MB P

// ---------------------------------------------------------------------------
// PTX helpers (baseline ISA: compiles for compute_103)
// ---------------------------------------------------------------------------
__device__ __forceinline__ uint32_t smem_u32(const void* p) {
    uint32_t a;
    asm("{ .reg .u64 t; cvta.to.shared.u64 t, %1; cvt.u32.u64 %0, t; }" : "=r"(a) : "l"(p));
    return a;
}
__device__ __forceinline__ void cp16(uint32_t dst, const void* src) {
    asm volatile("cp.async.cg.shared.global [%0], [%1], 16;" :: "r"(dst), "l"(src));
}
#define CP_COMMIT() asm volatile("cp.async.commit_group;" ::: "memory")
#define CP_WAIT1()  asm volatile("cp.async.wait_group 1;" ::: "memory")

__device__ __forceinline__ void ldm_x4(uint32_t* r, uint32_t addr) {
    asm volatile("ldmatrix.sync.aligned.m8n8.x4.shared.b16 {%0,%1,%2,%3}, [%4];"
                 : "=r"(r[0]), "=r"(r[1]), "=r"(r[2]), "=r"(r[3]) : "r"(addr));
}
__device__ __forceinline__ void ldm_x2(uint32_t* r, uint32_t addr) {
    asm volatile("ldmatrix.sync.aligned.m8n8.x2.shared.b16 {%0,%1}, [%2];"
                 : "=r"(r[0]), "=r"(r[1]) : "r"(addr));
}
__device__ __forceinline__ void ldm_x2_trans(uint32_t* r, uint32_t addr) {
    asm volatile("ldmatrix.sync.aligned.m8n8.x2.trans.shared.b16 {%0,%1}, [%2];"
                 : "=r"(r[0]), "=r"(r[1]) : "r"(addr));
}
__device__ __forceinline__ void mma_f16(float* c, const uint32_t* a, const uint32_t* b) {
    asm volatile(
        "mma.sync.aligned.m16n8k16.row.col.f32.f16.f16.f32 "
        "{%0,%1,%2,%3}, {%4,%5,%6,%7}, {%8,%9}, {%0,%1,%2,%3};"
        : "+f"(c[0]), "+f"(c[1]), "+f"(c[2]), "+f"(c[3])
        : "r"(a[0]), "r"(a[1]), "r"(a[2]), "r"(a[3]), "r"(b[0]), "r"(b[1]));
}

// ---------------------------------------------------------------------------
// Tiling: CTA 128x128, BK=64, 2-stage cp.async.
// A/B smem rows: 64 fp16 = 128 B + 16 pad = 144 B (conflict-free ldmatrix).
// ---------------------------------------------------------------------------
#define ROW_B   144
#define TILE_B  (128 * ROW_B)        // 18432
#define OB_OFF  TILE_B
#define STAGE_B (2 * TILE_B)         // 36864
#define SMEM_B  (2 * STAGE_B)        // 73728

// av: A = P [128 tok][64 k] rows 144 B; B = V [64 k][128 c] rows 272 B
#define AV_BROW   272
#define AV_BTILE  (64 * AV_BROW)     // 17408
#define AV_OB     TILE_B
#define AV_STAGE  (TILE_B + AV_BTILE)   // 35840
#define AV_SMEM   (2 * AV_STAGE)        // 71680

// ---------------------------------------------------------------------------
// fp16 single-product GEMM mainloop (A,B both [rows][k], K-major).
// Warp tile 64x32 (8 warps as 2x4). acc[mb][nb][ci].
// ---------------------------------------------------------------------------
template<int LDA, int LDB, int NCHUNK>
__device__ __forceinline__ void gemm_loop(
    float (&acc)[4][4][4], uint32_t sb,
    const __half* __restrict__ gA, const __half* __restrict__ gB)
{
    const int tid  = threadIdx.x;
    const int wid  = tid >> 5;
    const int lane = tid & 31;
    const int mw   = (wid >> 2) * 64;
    const int nw   = (wid & 3) * 32;

    const uint32_t a_l = (uint32_t)((lane & 15) * ROW_B + (lane >> 4) * 16);
    const uint32_t b_l = (uint32_t)((lane & 7) * ROW_B + ((lane >> 3) & 1) * 16);

    auto load_stage = [&](int chunk, int st) {
        const int k0 = chunk * 64;
        const uint32_t base = sb + (uint32_t)st * STAGE_B;
        #pragma unroll
        for (int t = 0; t < 4; t++) {
            int u = tid + t * 256;          // 0..1023
            int row = u >> 3, seg = u & 7;
            uint32_t so = base + (uint32_t)(row * ROW_B + seg * 16);
            cp16(so,          gA + (size_t)row * LDA + k0 + seg * 8);
            cp16(so + OB_OFF, gB + (size_t)row * LDB + k0 + seg * 8);
        }
        CP_COMMIT();
    };

    load_stage(0, 0);

    for (int c = 0; c < NCHUNK; c++) {
        if (c + 1 < NCHUNK) load_stage(c + 1, (c + 1) & 1);
        else                CP_COMMIT();
        CP_WAIT1();
        __syncthreads();

        const uint32_t stb = sb + (uint32_t)(c & 1) * STAGE_B;
        #pragma unroll
        for (int kk = 0; kk < 64; kk += 16) {
            uint32_t bf[4][2];
            #pragma unroll
            for (int nb = 0; nb < 4; nb++) {
                uint32_t ba = stb + OB_OFF + (uint32_t)((nw + nb * 8) * ROW_B + kk * 2) + b_l;
                ldm_x2(bf[nb], ba);
            }
            #pragma unroll
            for (int mb = 0; mb < 4; mb++) {
                uint32_t af[4];
                uint32_t aa = stb + (uint32_t)((mw + mb * 16) * ROW_B + kk * 2) + a_l;
                ldm_x4(af, aa);
                #pragma unroll
                for (int nb = 0; nb < 4; nb++)
                    mma_f16(acc[mb][nb], af, bf[nb]);
            }
        }
        __syncthreads();
    }
}

// ---------------------------------------------------------------------------
// Prep kernels
// ---------------------------------------------------------------------------
__global__ void convx_kernel(const float* __restrict__ x)
{
    size_t i = ((size_t)blockIdx.x * 256 + threadIdx.x) * 4;
    float4 v = *(const float4*)(x + i);
    __half2 a, b;
    a.x = __float2half(v.x); a.y = __float2half(v.y);
    b.x = __float2half(v.z); b.y = __float2half(v.w);
    *(__half2*)(g_xh + i)     = a;
    *(__half2*)(g_xh + i + 2) = b;
}

__global__ void convw_kernel(const float* __restrict__ wq,
                             const float* __restrict__ wk,
                             const float* __restrict__ wv)
{
    int idx = blockIdx.x * 256 + threadIdx.x;     // 640*512
    int n = idx >> 9, k = idx & 511;
    float v;
    if (n < 64)        v = wq[k * DQKD + n];
    else if (n < 128)  v = wk[k * DQKD + (n - 64)];
    else               v = wv[k * CH + (n - 128)];
    g_wt[idx] = __float2half(v);
}

// ---------------------------------------------------------------------------
// Kernel 1: QKV projection.  M=32768, N=640, K=512. grid (5, 256).
// ---------------------------------------------------------------------------
__global__ void __launch_bounds__(256, 2)
qkv_tc_kernel(const float* __restrict__ bq, const float* __restrict__ bk,
              const float* __restrict__ bv)
{
    extern __shared__ char dsmem[];
    const uint32_t sb = smem_u32(dsmem);
    const int m0 = blockIdx.y * 128;
    const int n0 = blockIdx.x * 128;

    float acc[4][4][4] = {};
    gemm_loop<CH, CH, 8>(acc, sb, g_xh + (size_t)m0 * CH, g_wt + (size_t)n0 * CH);

    const int wid = threadIdx.x >> 5, lane = threadIdx.x & 31;
    const int mw = (wid >> 2) * 64, nw = (wid & 3) * 32;
    const int gid = lane >> 2, tig = lane & 3;

    #pragma unroll
    for (int mb = 0; mb < 4; mb++)
        #pragma unroll
        for (int nb = 0; nb < 4; nb++)
            #pragma unroll
            for (int ci = 0; ci < 4; ci++) {
                int row = m0 + mw + mb * 16 + gid + ((ci >> 1) << 3);
                int col = n0 + nw + nb * 8 + tig * 2 + (ci & 1);
                float bias = (col < 64) ? bq[col] : (col < 128) ? bk[col - 64] : bv[col - 128];
                __half h = __float2half(acc[mb][nb][ci] + bias);
                if (col < 64)        g_qh[(size_t)row * DQKD + col] = h;
                else if (col < 128)  g_kh[(size_t)row * DQKD + (col - 64)] = h;
                else                 g_vh[(size_t)row * CH + (col - 128)] = h;
            }
}

// ---------------------------------------------------------------------------
// Kernel 2: scores.  S[b] = 0.125 * q @ k^T.  K=64 (one chunk). grid (8,8,32).
// ---------------------------------------------------------------------------
__global__ void __launch_bounds__(256, 2)
scores_tc_kernel()
{
    extern __shared__ char dsmem[];
    const uint32_t sb = smem_u32(dsmem);
    const int b = blockIdx.z;
    const int i0 = blockIdx.y * 128, j0 = blockIdx.x * 128;

    float acc[4][4][4] = {};
    gemm_loop<DQKD, DQKD, 1>(acc, sb,
                             g_qh + ((size_t)b * NTOK + i0) * DQKD,
                             g_kh + ((size_t)b * NTOK + j0) * DQKD);

    const int wid = threadIdx.x >> 5, lane = threadIdx.x & 31;
    const int mw = (wid >> 2) * 64, nw = (wid & 3) * 32;
    const int gid = lane >> 2, tig = lane & 3;

    float* srow = g_s + (size_t)b * NTOK * NTOK;
    #pragma unroll
    for (int mb = 0; mb < 4; mb++)
        #pragma unroll
        for (int nb = 0; nb < 4; nb++)
            #pragma unroll
            for (int h = 0; h < 2; h++) {
                int row = i0 + mw + mb * 16 + gid + h * 8;
                int col = j0 + nw + nb * 8 + tig * 2;
                float2 o;
                o.x = acc[mb][nb][h * 2 + 0] * 0.125f;
                o.y = acc[mb][nb][h * 2 + 1] * 0.125f;
                *(float2*)(srow + (size_t)row * NTOK + col) = o;
            }
}

// ---------------------------------------------------------------------------
// Kernel 3: row softmax, writes P as fp16
// ---------------------------------------------------------------------------
__global__ void __launch_bounds__(256)
softmax_kernel()
{
    const size_t rb = (size_t)blockIdx.x * NTOK;
    const int tid = threadIdx.x;
    __shared__ float redm[8];
    __shared__ float reds[8];

    float4 v = *(const float4*)(g_s + rb + tid * 4);
    float mx = fmaxf(fmaxf(v.x, v.y), fmaxf(v.z, v.w));
    #pragma unroll
    for (int o = 16; o > 0; o >>= 1) mx = fmaxf(mx, __shfl_xor_sync(~0u, mx, o));
    if ((tid & 31) == 0) redm[tid >> 5] = mx;
    __syncthreads();
    mx = redm[0];
    #pragma unroll
    for (int i = 1; i < 8; i++) mx = fmaxf(mx, redm[i]);

    v.x = __expf(v.x - mx); v.y = __expf(v.y - mx);
    v.z = __expf(v.z - mx); v.w = __expf(v.w - mx);
    float sum = (v.x + v.y) + (v.z + v.w);
    #pragma unroll
    for (int o = 16; o > 0; o >>= 1) sum += __shfl_xor_sync(~0u, sum, o);
    if ((tid & 31) == 0) reds[tid >> 5] = sum;
    __syncthreads();
    sum = reds[0];
    #pragma unroll
    for (int i = 1; i < 8; i++) sum += reds[i];
    float inv = 1.0f / sum;

    __half2 p01, p23;
    p01.x = __float2half(v.x * inv); p01.y = __float2half(v.y * inv);
    p23.x = __float2half(v.z * inv); p23.y = __float2half(v.w * inv);
    *(__half2*)(g_p + rb + tid * 4)     = p01;
    *(__half2*)(g_p + rb + tid * 4 + 2) = p23;
}

// ---------------------------------------------------------------------------
// Kernel 4: O = P @ V + x.  A = P [tok][k] K-major; B = V [k][c] row-major
// via ldmatrix.trans.  BK=64, grid (4, 8, 32).
// ---------------------------------------------------------------------------
__global__ void __launch_bounds__(256, 2)
av_tc_kernel(const float* __restrict__ x, float* __restrict__ out)
{
    extern __shared__ char dsmem[];
    const uint32_t sb = smem_u32(dsmem);
    const int b = blockIdx.z;
    const int i0 = blockIdx.y * 128, c0 = blockIdx.x * 128;
    const int tid = threadIdx.x;
    const int wid = tid >> 5, lane = tid & 31;
    const int mw = (wid >> 2) * 64, nw = (wid & 3) * 32;

    const __half* pA = g_p + ((size_t)b * NTOK + i0) * NTOK;
    const __half* pB = g_vh + (size_t)b * NTOK * CH + c0;

    const uint32_t a_l = (uint32_t)((lane & 15) * ROW_B + (lane >> 4) * 16);
    const uint32_t b_l = (uint32_t)((lane & 15) * AV_BROW);

    auto load_stage = [&](int chunk, int st) {
        const int k0 = chunk * 64;
        const uint32_t base = sb + (uint32_t)st * AV_STAGE;
        // A: 128 rows x 128 B
        #pragma unroll
        for (int t = 0; t < 4; t++) {
            int u = tid + t * 256;
            int row = u >> 3, seg = u & 7;
            cp16(base + (uint32_t)(row * ROW_B + seg * 16),
                 pA + (size_t)row * NTOK + k0 + seg * 8);
        }
        // B: 64 k-rows x 256 B
        #pragma unroll
        for (int t = 0; t < 4; t++) {
            int u = tid + t * 256;
            int row = u >> 4, seg = u & 15;
            cp16(base + AV_OB + (uint32_t)(row * AV_BROW + seg * 16),
                 pB + (size_t)(k0 + row) * CH + seg * 8);
        }
        CP_COMMIT();
    };

    float acc[4][4][4] = {};
    load_stage(0, 0);

    for (int c = 0; c < 16; c++) {
        if (c + 1 < 16) load_stage(c + 1, (c + 1) & 1);
        else            CP_COMMIT();
        CP_WAIT1();
        __syncthreads();

        const uint32_t stb = sb + (uint32_t)(c & 1) * AV_STAGE;
        #pragma unroll
        for (int kk = 0; kk < 64; kk += 16) {
            uint32_t bf[4][2];
            #pragma unroll
            for (int nb = 0; nb < 4; nb++) {
                uint32_t ba = stb + AV_OB + (uint32_t)(kk * AV_BROW + (nw + nb * 8) * 2) + b_l;
                ldm_x2_trans(bf[nb], ba);
            }
            #pragma unroll
            for (int mb = 0; mb < 4; mb++) {
                uint32_t af[4];
                uint32_t aa = stb + (uint32_t)((mw + mb * 16) * ROW_B + kk * 2) + a_l;
                ldm_x4(af, aa);
                #pragma unroll
                for (int nb = 0; nb < 4; nb++)
                    mma_f16(acc[mb][nb], af, bf[nb]);
            }
        }
        __syncthreads();
    }

    const int gid = lane >> 2, tig = lane & 3;
    #pragma unroll
    for (int mb = 0; mb < 4; mb++)
        #pragma unroll
        for (int nb = 0; nb < 4; nb++)
            #pragma unroll
            for (int h = 0; h < 2; h++) {
                int row = i0 + mw + mb * 16 + gid + h * 8;
                int col = c0 + nw + nb * 8 + tig * 2;
                size_t o = ((size_t)b * NTOK + row) * CH + col;
                float2 xv = *(const float2*)(x + o);
                float2 ov;
                ov.x = acc[mb][nb][h * 2 + 0] + xv.x;
                ov.y = acc[mb][nb][h * 2 + 1] + xv.y;
                *(float2*)(out + o) = ov;
            }
}

// ---------------------------------------------------------------------------
extern "C" void kernel_launch(void* const* d_in, const int* in_sizes, int n_in,
                              void* d_out, int out_size)
{
    const float* x  = (const float*)d_in[0];
    const float* wq = (const float*)d_in[1];
    const float* bq = (const float*)d_in[2];
    const float* wk = (const float*)d_in[3];
    const float* bk = (const float*)d_in[4];
    const float* wv = (const float*)d_in[5];
    const float* bv = (const float*)d_in[6];
    float* out = (float*)d_out;

    cudaFuncSetAttribute(qkv_tc_kernel,    cudaFuncAttributeMaxDynamicSharedMemorySize, SMEM_B);
    cudaFuncSetAttribute(scores_tc_kernel, cudaFuncAttributeMaxDynamicSharedMemorySize, SMEM_B);
    cudaFuncSetAttribute(av_tc_kernel,     cudaFuncAttributeMaxDynamicSharedMemorySize, AV_SMEM);

    convx_kernel<<<16384, 256>>>(x);
    convw_kernel<<<1280, 256>>>(wq, wk, wv);
    qkv_tc_kernel<<<dim3(5, 256), 256, SMEM_B>>>(bq, bk, bv);
    scores_tc_kernel<<<dim3(8, 8, 32), 256, SMEM_B>>>();
    softmax_kernel<<<BATCH * NTOK, 256>>>();
    av_tc_kernel<<<dim3(4, 8, 32), 256, AV_SMEM>>>(x, out);
}

// round 8
// speedup vs baseline: 6.2044x; 1.0774x over previous
#include <cuda_runtime.h>
#include <cuda_fp16.h>
#include <cstdint>

#define BATCH 32
#define NTOK  1024
#define CH    512
#define DQKD  64

// ---------------------------------------------------------------------------
// Device-global scratch (fp16 operands)
// ---------------------------------------------------------------------------
__device__ __align__(128) __half g_xh[(size_t)BATCH * NTOK * CH];     // 32 MB
__device__ __align__(128) __half g_wt[640 * CH];                      // W^T [n][k]
__device__ __align__(128) __half g_qh[(size_t)BATCH * NTOK * DQKD];
__device__ __align__(128) __half g_kh[(size_t)BATCH * NTOK * DQKD];
__device__ __align__(128) __half g_vh[(size_t)BATCH * NTOK * CH];     // V [b][m][c]
__device__ __align__(128) __half g_p[(size_t)BATCH * NTOK * NTOK];    // 64 MB P

// ---------------------------------------------------------------------------
// PTX helpers (baseline ISA: compiles for compute_103)
// ---------------------------------------------------------------------------
__device__ __forceinline__ uint32_t smem_u32(const void* p) {
    uint32_t a;
    asm("{ .reg .u64 t; cvta.to.shared.u64 t, %1; cvt.u32.u64 %0, t; }" : "=r"(a) : "l"(p));
    return a;
}
__device__ __forceinline__ void cp16(uint32_t dst, const void* src) {
    asm volatile("cp.async.cg.shared.global [%0], [%1], 16;" :: "r"(dst), "l"(src));
}
#define CP_COMMIT() asm volatile("cp.async.commit_group;" ::: "memory")
#define CP_WAIT1()  asm volatile("cp.async.wait_group 1;" ::: "memory")

__device__ __forceinline__ void ldm_x4(uint32_t* r, uint32_t addr) {
    asm volatile("ldmatrix.sync.aligned.m8n8.x4.shared.b16 {%0,%1,%2,%3}, [%4];"
                 : "=r"(r[0]), "=r"(r[1]), "=r"(r[2]), "=r"(r[3]) : "r"(addr));
}
__device__ __forceinline__ void ldm_x2(uint32_t* r, uint32_t addr) {
    asm volatile("ldmatrix.sync.aligned.m8n8.x2.shared.b16 {%0,%1}, [%2];"
                 : "=r"(r[0]), "=r"(r[1]) : "r"(addr));
}
__device__ __forceinline__ void ldm_x4_trans(uint32_t* r, uint32_t addr) {
    asm volatile("ldmatrix.sync.aligned.m8n8.x4.trans.shared.b16 {%0,%1,%2,%3}, [%4];"
                 : "=r"(r[0]), "=r"(r[1]), "=r"(r[2]), "=r"(r[3]) : "r"(addr));
}
__device__ __forceinline__ void mma_f16(float* c, const uint32_t* a, const uint32_t* b) {
    asm volatile(
        "mma.sync.aligned.m16n8k16.row.col.f32.f16.f16.f32 "
        "{%0,%1,%2,%3}, {%4,%5,%6,%7}, {%8,%9}, {%0,%1,%2,%3};"
        : "+f"(c[0]), "+f"(c[1]), "+f"(c[2]), "+f"(c[3])
        : "r"(a[0]), "r"(a[1]), "r"(a[2]), "r"(a[3]), "r"(b[0]), "r"(b[1]));
}

// ---------------------------------------------------------------------------
// qkv tiling (unchanged): CTA 128x128, BK=64, 2-stage, rows 144 B.
// ---------------------------------------------------------------------------
#define ROW_B   144
#define TILE_B  (128 * ROW_B)        // 18432
#define OB_OFF  TILE_B
#define STAGE_B (2 * TILE_B)         // 36864
#define SMEM_B  (2 * STAGE_B)        // 73728

// av: A = P [128 tok][64 k] rows 144 B; B = V [64 k][128 c] rows 272 B
#define AV_BROW   272
#define AV_BTILE  (64 * AV_BROW)     // 17408
#define AV_OB     TILE_B
#define AV_STAGE  (TILE_B + AV_BTILE)   // 35840
#define AV_SMEM   (2 * AV_STAGE)        // 71680

// probs: q tile [32][64] rows 144 B; k tiles double-buffered [128][64] rows 144 B;
// Ptilde f32 [32][1028] (padded: row stride 1028 words -> conflict-free stores)
#define PR_Q      0
#define PR_QSZ    (32 * ROW_B)                    // 4608
#define PR_K      PR_QSZ
#define PR_KSZ    (128 * ROW_B)                   // 18432
#define PR_P      (PR_K + 2 * PR_KSZ)             // 41472
#define PR_ROWW   1028
#define PR_PSZ    (32 * PR_ROWW * 4)              // 131584
#define PR_SMEM   (PR_P + PR_PSZ)                 // 173056

// ---------------------------------------------------------------------------
// fp16 GEMM mainloop for qkv (A,B both [rows][k] K-major), 256 thr, warp 64x32
// ---------------------------------------------------------------------------
template<int LDA, int LDB, int NCHUNK>
__device__ __forceinline__ void gemm_loop(
    float (&acc)[4][4][4], uint32_t sb,
    const __half* __restrict__ gA, const __half* __restrict__ gB)
{
    const int tid  = threadIdx.x;
    const int wid  = tid >> 5;
    const int lane = tid & 31;
    const int mw   = (wid >> 2) * 64;
    const int nw   = (wid & 3) * 32;

    const uint32_t a_l = (uint32_t)((lane & 15) * ROW_B + (lane >> 4) * 16);
    const uint32_t b_l = (uint32_t)((lane & 7) * ROW_B + ((lane >> 3) & 1) * 16);

    auto load_stage = [&](int chunk, int st) {
        const int k0 = chunk * 64;
        const uint32_t base = sb + (uint32_t)st * STAGE_B;
        #pragma unroll
        for (int t = 0; t < 4; t++) {
            int u = tid + t * 256;
            int row = u >> 3, seg = u & 7;
            uint32_t so = base + (uint32_t)(row * ROW_B + seg * 16);
            cp16(so,          gA + (size_t)row * LDA + k0 + seg * 8);
            cp16(so + OB_OFF, gB + (size_t)row * LDB + k0 + seg * 8);
        }
        CP_COMMIT();
    };

    load_stage(0, 0);

    for (int c = 0; c < NCHUNK; c++) {
        if (c + 1 < NCHUNK) load_stage(c + 1, (c + 1) & 1);
        else                CP_COMMIT();
        CP_WAIT1();
        __syncthreads();

        const uint32_t stb = sb + (uint32_t)(c & 1) * STAGE_B;
        #pragma unroll
        for (int kk = 0; kk < 64; kk += 16) {
            uint32_t bf[4][2];
            #pragma unroll
            for (int nb = 0; nb < 4; nb++)
                ldm_x2(bf[nb], stb + OB_OFF + (uint32_t)((nw + nb * 8) * ROW_B + kk * 2) + b_l);
            #pragma unroll
            for (int mb = 0; mb < 4; mb++) {
                uint32_t af[4];
                ldm_x4(af, stb + (uint32_t)((mw + mb * 16) * ROW_B + kk * 2) + a_l);
                #pragma unroll
                for (int nb = 0; nb < 4; nb++)
                    mma_f16(acc[mb][nb], af, bf[nb]);
            }
        }
        __syncthreads();
    }
}

// ---------------------------------------------------------------------------
// Prep kernels
// ---------------------------------------------------------------------------
__global__ void convx_kernel(const float* __restrict__ x)
{
    size_t i = ((size_t)blockIdx.x * 256 + threadIdx.x) * 4;
    float4 v = *(const float4*)(x + i);
    __half2 a, b;
    a.x = __float2half(v.x); a.y = __float2half(v.y);
    b.x = __float2half(v.z); b.y = __float2half(v.w);
    *(__half2*)(g_xh + i)     = a;
    *(__half2*)(g_xh + i + 2) = b;
}

__global__ void convw_kernel(const float* __restrict__ wq,
                             const float* __restrict__ wk,
                             const float* __restrict__ wv)
{
    int idx = blockIdx.x * 256 + threadIdx.x;     // 640*512
    int n = idx >> 9, k = idx & 511;
    float v;
    if (n < 64)        v = wq[k * DQKD + n];
    else if (n < 128)  v = wk[k * DQKD + (n - 64)];
    else               v = wv[k * CH + (n - 128)];
    g_wt[idx] = __float2half(v);
}

// ---------------------------------------------------------------------------
// Kernel 1: QKV projection.  M=32768, N=640, K=512. grid (5, 256).
// ---------------------------------------------------------------------------
__global__ void __launch_bounds__(256, 2)
qkv_tc_kernel(const float* __restrict__ bq, const float* __restrict__ bk,
              const float* __restrict__ bv)
{
    extern __shared__ char dsmem[];
    const uint32_t sb = smem_u32(dsmem);
    const int m0 = blockIdx.y * 128;
    const int n0 = blockIdx.x * 128;

    float acc[4][4][4] = {};
    gemm_loop<CH, CH, 8>(acc, sb, g_xh + (size_t)m0 * CH, g_wt + (size_t)n0 * CH);

    const int wid = threadIdx.x >> 5, lane = threadIdx.x & 31;
    const int mw = (wid >> 2) * 64, nw = (wid & 3) * 32;
    const int gid = lane >> 2, tig = lane & 3;

    #pragma unroll
    for (int mb = 0; mb < 4; mb++)
        #pragma unroll
        for (int nb = 0; nb < 4; nb++)
            #pragma unroll
            for (int ci = 0; ci < 4; ci++) {
                int row = m0 + mw + mb * 16 + gid + ((ci >> 1) << 3);
                int col = n0 + nw + nb * 8 + tig * 2 + (ci & 1);
                float bias = (col < 64) ? bq[col] : (col < 128) ? bk[col - 64] : bv[col - 128];
                __half h = __float2half(acc[mb][nb][ci] + bias);
                if (col < 64)        g_qh[(size_t)row * DQKD + col] = h;
                else if (col < 128)  g_kh[(size_t)row * DQKD + (col - 64)] = h;
                else                 g_vh[(size_t)row * CH + (col - 128)] = h;
            }
}

// ---------------------------------------------------------------------------
// Kernel 2: FUSED scores + softmax -> P (fp16).
// CTA = 32 q-rows x all 1024 kv.  grid (32 i-tiles, 32 batches), 256 thr.
// No max-subtraction: scores*0.125 has |s| <~ 20, exp safe in f32.
// Unnormalized exp kept in smem f32 [32][1028]; row-sum + normalize at end.
// ---------------------------------------------------------------------------
__global__ void __launch_bounds__(256)
probs_kernel()
{
    extern __shared__ char dsmem[];
    const uint32_t sb = smem_u32(dsmem);
    float* Ps = (float*)(dsmem + PR_P);

    const int tid = threadIdx.x;
    const int wid = tid >> 5, lane = tid & 31;
    const int b = blockIdx.y;
    const int i0 = blockIdx.x * 32;

    const __half* gq = g_qh + ((size_t)b * NTOK + i0) * DQKD;
    const __half* gk = g_kh + (size_t)b * NTOK * DQKD;

    // load q tile [32][64] + k tile 0 [128][64]
    {
        int row = tid >> 3, seg = tid & 7;          // 256 = 32 rows x 8 segs
        cp16(sb + PR_Q + (uint32_t)(row * ROW_B + seg * 16),
             gq + (size_t)row * DQKD + seg * 8);
        #pragma unroll
        for (int t = 0; t < 4; t++) {
            int u = tid + t * 256;
            int r = u >> 3, s = u & 7;
            cp16(sb + PR_K + (uint32_t)(r * ROW_B + s * 16),
                 gk + (size_t)r * DQKD + s * 8);
        }
        CP_COMMIT();
    }

    const int mw = (wid >> 2) * 16;                 // 2 row groups of 16
    const int nw = (wid & 3) * 32;                  // 4 col groups of 32
    const uint32_t a_l = (uint32_t)((lane & 15) * ROW_B + (lane >> 4) * 16);
    const uint32_t b_l = (uint32_t)((lane & 7) * ROW_B + ((lane >> 3) & 1) * 16);
    const int gid = lane >> 2, tig = lane & 3;

    uint32_t af[4][4];
    bool a_loaded = false;

    for (int j = 0; j < 8; j++) {
        if (j + 1 < 8) {                            // prefetch next k tile
            const __half* gkn = gk + (size_t)(j + 1) * 128 * DQKD;
            const uint32_t kb = sb + PR_K + (uint32_t)(((j + 1) & 1) * PR_KSZ);
            #pragma unroll
            for (int t = 0; t < 4; t++) {
                int u = tid + t * 256;
                int r = u >> 3, s = u & 7;
                cp16(kb + (uint32_t)(r * ROW_B + s * 16), gkn + (size_t)r * DQKD + s * 8);
            }
            CP_COMMIT();
        } else CP_COMMIT();
        CP_WAIT1();
        __syncthreads();

        if (!a_loaded) {                            // q frags once (after first wait)
            #pragma unroll
            for (int kk = 0; kk < 4; kk++)
                ldm_x4(af[kk], sb + PR_Q + (uint32_t)(mw * ROW_B + kk * 32) + a_l);
            a_loaded = true;
        }

        const uint32_t kbb = sb + PR_K + (uint32_t)((j & 1) * PR_KSZ);
        float acc[4][4] = {};
        #pragma unroll
        for (int kk = 0; kk < 4; kk++) {
            #pragma unroll
            for (int nb = 0; nb < 4; nb++) {
                uint32_t bf[2];
                ldm_x2(bf, kbb + (uint32_t)((nw + nb * 8) * ROW_B + kk * 32) + b_l);
                mma_f16(acc[nb], af[kk], bf);
            }
        }
        // exp + store to Ps
        #pragma unroll
        for (int nb = 0; nb < 4; nb++)
            #pragma unroll
            for (int ci = 0; ci < 4; ci++) {
                int row = mw + gid + ((ci >> 1) << 3);
                int col = j * 128 + nw + nb * 8 + tig * 2 + (ci & 1);
                Ps[row * PR_ROWW + col] = __expf(acc[nb][ci] * 0.125f);
            }
        __syncthreads();
    }

    // per-row sum + normalize + fp16 store. warp w -> rows 4w..4w+3.
    #pragma unroll
    for (int r = 0; r < 4; r++) {
        const int row = wid * 4 + r;
        const float* prow = Ps + row * PR_ROWW;
        float s = 0.f;
        #pragma unroll
        for (int it = 0; it < 8; it++) {
            float4 v = *(const float4*)(prow + it * 128 + lane * 4);
            s += (v.x + v.y) + (v.z + v.w);
        }
        #pragma unroll
        for (int o = 16; o > 0; o >>= 1) s += __shfl_xor_sync(~0u, s, o);
        const float inv = 1.0f / s;
        __half* orow = g_p + ((size_t)b * NTOK + i0 + row) * NTOK;
        #pragma unroll
        for (int it = 0; it < 8; it++) {
            float4 v = *(const float4*)(prow + it * 128 + lane * 4);
            __half2 h0, h1;
            h0.x = __float2half(v.x * inv); h0.y = __float2half(v.y * inv);
            h1.x = __float2half(v.z * inv); h1.y = __float2half(v.w * inv);
            uint2 pk;
            pk.x = *(uint32_t*)&h0; pk.y = *(uint32_t*)&h1;
            *(uint2*)(orow + it * 128 + lane * 4) = pk;
        }
    }
}

// ---------------------------------------------------------------------------
// Kernel 3: O = P @ V + x.  128 threads, 4 warps (2x2), warp tile 64x64.
// A = P [tok][k] K-major; B = V [k][c] via ldmatrix.x4.trans.  grid (4,8,32).
// ---------------------------------------------------------------------------
__global__ void __launch_bounds__(128, 2)
av_tc_kernel(const float* __restrict__ x, float* __restrict__ out)
{
    extern __shared__ char dsmem[];
    const uint32_t sb = smem_u32(dsmem);
    const int b = blockIdx.z;
    const int i0 = blockIdx.y * 128, c0 = blockIdx.x * 128;
    const int tid = threadIdx.x;
    const int wid = tid >> 5, lane = tid & 31;
    const int mw = (wid >> 1) * 64, nw = (wid & 1) * 64;

    const __half* pA = g_p + ((size_t)b * NTOK + i0) * NTOK;
    const __half* pB = g_vh + (size_t)b * NTOK * CH + c0;

    const uint32_t a_l = (uint32_t)((lane & 15) * ROW_B + (lane >> 4) * 16);
    const uint32_t b_l = (uint32_t)((lane & 15) * AV_BROW + (lane >> 4) * 16);

    auto load_stage = [&](int chunk, int st) {
        const int k0 = chunk * 64;
        const uint32_t base = sb + (uint32_t)st * AV_STAGE;
        #pragma unroll
        for (int t = 0; t < 8; t++) {               // A: 128 rows x 8 segs
            int u = tid + t * 128;
            int row = u >> 3, seg = u & 7;
            cp16(base + (uint32_t)(row * ROW_B + seg * 16),
                 pA + (size_t)row * NTOK + k0 + seg * 8);
        }
        #pragma unroll
        for (int t = 0; t < 8; t++) {               // B: 64 rows x 16 segs
            int u = tid + t * 128;
            int row = u >> 4, seg = u & 15;
            cp16(base + AV_OB + (uint32_t)(row * AV_BROW + seg * 16),
                 pB + (size_t)(k0 + row) * CH + seg * 8);
        }
        CP_COMMIT();
    };

    float acc[4][8][4] = {};
    load_stage(0, 0);

    for (int c = 0; c < 16; c++) {
        if (c + 1 < 16) load_stage(c + 1, (c + 1) & 1);
        else            CP_COMMIT();
        CP_WAIT1();
        __syncthreads();

        const uint32_t stb = sb + (uint32_t)(c & 1) * AV_STAGE;
        #pragma unroll
        for (int kk = 0; kk < 64; kk += 16) {
            uint32_t bf[4][4];
            #pragma unroll
            for (int nb2 = 0; nb2 < 4; nb2++)       // 4 x ldm_x4_trans = 8 n8-frags
                ldm_x4_trans(bf[nb2],
                    stb + AV_OB + (uint32_t)(kk * AV_BROW + (nw + nb2 * 16) * 2) + b_l);
            #pragma unroll
            for (int mb = 0; mb < 4; mb++) {
                uint32_t af[4];
                ldm_x4(af, stb + (uint32_t)((mw + mb * 16) * ROW_B + kk * 2) + a_l);
                #pragma unroll
                for (int nb2 = 0; nb2 < 4; nb2++) {
                    mma_f16(acc[mb][nb2 * 2 + 0], af, bf[nb2] + 0);
                    mma_f16(acc[mb][nb2 * 2 + 1], af, bf[nb2] + 2);
                }
            }
        }
        __syncthreads();
    }

    const int gid = lane >> 2, tig = lane & 3;
    #pragma unroll
    for (int mb = 0; mb < 4; mb++)
        #pragma unroll
        for (int nb = 0; nb < 8; nb++)
            #pragma unroll
            for (int h = 0; h < 2; h++) {
                int row = i0 + mw + mb * 16 + gid + h * 8;
                int col = c0 + nw + nb * 8 + tig * 2;
                size_t o = ((size_t)b * NTOK + row) * CH + col;
                float2 xv = *(const float2*)(x + o);
                float2 ov;
                ov.x = acc[mb][nb][h * 2 + 0] + xv.x;
                ov.y = acc[mb][nb][h * 2 + 1] + xv.y;
                *(float2*)(out + o) = ov;
            }
}

// ---------------------------------------------------------------------------
extern "C" void kernel_launch(void* const* d_in, const int* in_sizes, int n_in,
                              void* d_out, int out_size)
{
    const float* x  = (const float*)d_in[0];
    const float* wq = (const float*)d_in[1];
    const float* bq = (const float*)d_in[2];
    const float* wk = (const float*)d_in[3];
    const float* bk = (const float*)d_in[4];
    const float* wv = (const float*)d_in[5];
    const float* bv = (const float*)d_in[6];
    float* out = (float*)d_out;

    cudaFuncSetAttribute(qkv_tc_kernel, cudaFuncAttributeMaxDynamicSharedMemorySize, SMEM_B);
    cudaFuncSetAttribute(probs_kernel,  cudaFuncAttributeMaxDynamicSharedMemorySize, PR_SMEM);
    cudaFuncSetAttribute(av_tc_kernel,  cudaFuncAttributeMaxDynamicSharedMemorySize, AV_SMEM);

    convx_kernel<<<16384, 256>>>(x);
    convw_kernel<<<1280, 256>>>(wq, wk, wv);
    qkv_tc_kernel<<<dim3(5, 256), 256, SMEM_B>>>(bq, bk, bv);
    probs_kernel<<<dim3(32, 32), 256, PR_SMEM>>>();
    av_tc_kernel<<<dim3(4, 8, 32), 128, AV_SMEM>>>(x, out);
}